// round 4
// baseline (speedup 1.0000x reference)
#include <cuda_runtime.h>

// Fixed problem structure (M=512 checks, N=1024 vars, SHIFTS=(0,7,101)):
//   E = 3072 edges, check degree 6, var degree 3.
//   edges sorted by (check,var) => check c owns edges [6c, 6c+6).
#define ITERS 5
#define MCHK  512
#define NVAR  1024
#define NEDGE 3072

#define LOG2E 1.4426950408889634f
#define LN2   0.6931471805599453f

// Batch-invariant scratch, slot-major [j][c] for coalescing.
// Messages circulate in log2 units (see round-2 notes): g_w2 = w_iter,
// g_lt = llr_iter*log2e, g_wf = w_final*ln2.
__device__ float2 g_w2  [ITERS * NEDGE];
__device__ float  g_lt  [ITERS * NEDGE];
__device__ int2   g_sib [NEDGE];          // sibling edge ids, translated to j*512+c
__device__ int    g_ev  [NEDGE];
__device__ int    g_fidx[NEDGE];
__device__ float  g_wf  [NEDGE];

__global__ void prepack_kernel(const float* __restrict__ w_iter,
                               const float* __restrict__ llr_iter,
                               const int*   __restrict__ vs_idx,
                               const int*   __restrict__ edge_var,
                               const int*   __restrict__ fin_idx,
                               const float* __restrict__ w_final)
{
    const int c = threadIdx.x;
    const int t = blockIdx.x;
#pragma unroll
    for (int j = 0; j < 6; ++j) {
        const int e = 6 * c + j;
        g_w2[t * NEDGE + j * MCHK + c] =
            make_float2(w_iter[t * 2 * NEDGE + 2 * e],
                        w_iter[t * 2 * NEDGE + 2 * e + 1]);
        g_lt[t * NEDGE + j * MCHK + c] = llr_iter[t * NVAR + edge_var[e]] * LOG2E;
    }
    if (t == 0) {
#pragma unroll
        for (int j = 0; j < 6; ++j) {
            const int e  = 6 * c + j;
            const int s0 = vs_idx[2 * e];
            const int s1 = vs_idx[2 * e + 1];
            g_sib[j * MCHK + c] = make_int2((s0 % 6) * MCHK + s0 / 6,
                                            (s1 % 6) * MCHK + s1 / 6);
            g_ev[j * MCHK + c]  = edge_var[e];
        }
#pragma unroll
        for (int k = 0; k < 2; ++k)
#pragma unroll
            for (int p = 0; p < 3; ++p) {
                const int v = c + MCHK * k;
                const int q = 3 * v + p;
                const int e = fin_idx[q];
                g_fidx[(k * 3 + p) * MCHK + c] = (e % 6) * MCHK + e / 6;
                g_wf  [(k * 3 + p) * MCHK + c] = w_final[q] * LN2;
            }
    }
}

// Two batch items per thread: batch-invariant weight loads hit registers twice,
// doubled ILP per warp, half the barriers per item.
__global__ __launch_bounds__(512, 1)
void bp_decode2_kernel(const float* __restrict__ llr,        // [B, N]
                       const float* __restrict__ llr_final,  // [N]
                       float*       __restrict__ out,        // [B, N]
                       int B)
{
    __shared__ float sm[2][2][NEDGE];   // [buffer][item][edge], 48 KB

    const int c  = threadIdx.x;
    const int b0 = 2 * blockIdx.x;
    const int has2 = (b0 + 1 < B);
    const float* __restrict__ llr0 = llr + (size_t)b0 * NVAR;
    const float* __restrict__ llr1 = llr + (size_t)(b0 + has2) * NVAR;

    int2  sib[6];
    float lv0[6], lv1[6];
#pragma unroll
    for (int j = 0; j < 6; ++j) {
        sib[j] = g_sib[j * MCHK + c];
        const int v = g_ev[j * MCHK + c];
        lv0[j] = __ldg(&llr0[v]);
        lv1[j] = __ldg(&llr1[v]);
    }

    float c2v0[6], c2v1[6];
#pragma unroll
    for (int j = 0; j < 6; ++j) { c2v0[j] = 0.0f; c2v1[j] = 0.0f; }

    int cur = 0;
    for (int t = 0; t < ITERS; ++t) {
        // publish messages (conflict-free STS), single barrier per iteration
#pragma unroll
        for (int j = 0; j < 6; ++j) {
            sm[cur][0][j * MCHK + c] = c2v0[j];
            sm[cur][1][j * MCHK + c] = c2v1[j];
        }
        __syncthreads();

        const float2* __restrict__ w2 = g_w2 + t * NEDGE;
        const float*  __restrict__ lt = g_lt + t * NEDGE;

        // Variable update (rational form): v2c = (2^x-1)/(2^x+1)
        float n0[6], d0[6], n1[6], d1[6];
#pragma unroll
        for (int j = 0; j < 6; ++j) {
            const float2 w  = w2[j * MCHK + c];      // loaded once, used twice
            const float  lj = lt[j * MCHK + c];

            float x0 = sm[cur][0][sib[j].x] * w.x + sm[cur][0][sib[j].y] * w.y
                     + lv0[j] * lj;
            float x1 = sm[cur][1][sib[j].x] * w.x + sm[cur][1][sib[j].y] * w.y
                     + lv1[j] * lj;
            x0 = fminf(fmaxf(x0, -25.0f), 25.0f);    // overflow headroom for prod^5
            x1 = fminf(fmaxf(x1, -25.0f), 25.0f);
            const float e0 = exp2f(x0);
            const float e1 = exp2f(x1);
            n0[j] = e0 - 1.0f;  d0[j] = e0 + 1.0f;
            n1[j] = e1 - 1.0f;  d1[j] = e1 + 1.0f;
        }

        // Check update: exclusive products tracked as P/Q;
        //   c2v_l2 = log2(Q+P) - log2(Q-P)
        float sn0[6], sd0[6], sn1[6], sd1[6];
        sn0[5] = sd0[5] = sn1[5] = sd1[5] = 1.0f;
#pragma unroll
        for (int j = 4; j >= 0; --j) {
            sn0[j] = sn0[j + 1] * n0[j + 1];  sd0[j] = sd0[j + 1] * d0[j + 1];
            sn1[j] = sn1[j + 1] * n1[j + 1];  sd1[j] = sd1[j + 1] * d1[j + 1];
        }
        float pn0 = 0.9995f, pd0 = 1.0f, pn1 = 0.9995f, pd1 = 1.0f;
#pragma unroll
        for (int j = 0; j < 6; ++j) {
            const float P0 = pn0 * sn0[j], Q0 = pd0 * sd0[j];
            const float P1 = pn1 * sn1[j], Q1 = pd1 * sd1[j];
            c2v0[j] = __log2f(Q0 + P0) - __log2f(Q0 - P0);
            c2v1[j] = __log2f(Q1 + P1) - __log2f(Q1 - P1);
            pn0 *= n0[j];  pd0 *= d0[j];
            pn1 *= n1[j];  pd1 *= d1[j];
        }
        cur ^= 1;
    }

    // Epilogue: publish final messages, then 2 vars x 2 items per thread.
#pragma unroll
    for (int j = 0; j < 6; ++j) {
        sm[cur][0][j * MCHK + c] = c2v0[j];
        sm[cur][1][j * MCHK + c] = c2v1[j];
    }
    __syncthreads();

    float* __restrict__ out0 = out + (size_t)b0 * NVAR;
    float* __restrict__ out1 = out + (size_t)(b0 + has2) * NVAR;
#pragma unroll
    for (int k = 0; k < 2; ++k) {
        const int v = c + MCHK * k;
        float m0 = 0.0f, m1 = 0.0f;
#pragma unroll
        for (int p = 0; p < 3; ++p) {
            const int q  = (k * 3 + p) * MCHK + c;   // coalesced
            const int fi = g_fidx[q];
            const float wf = g_wf[q];                // loaded once, used twice
            m0 += sm[cur][0][fi] * wf;
            m1 += sm[cur][1][fi] * wf;
        }
        const float lf = llr_final[v];
        m0 += __ldg(&llr0[v]) * lf;
        m1 += __ldg(&llr1[v]) * lf;
        out0[v] = __fdividef(1.0f, 1.0f + __expf(-m0));
        if (has2) out1[v] = __fdividef(1.0f, 1.0f + __expf(-m1));
    }
}

extern "C" void kernel_launch(void* const* d_in, const int* in_sizes, int n_in,
                              void* d_out, int out_size)
{
    // metadata order: llr, w_iter, llr_iter, w_final, llr_final,
    //                 v_sum_idx, seg_vsum, c_prod_idx, seg_cprod,
    //                 final_idx, seg_final, edge_var
    const float* llr       = (const float*)d_in[0];
    const float* w_iter    = (const float*)d_in[1];
    const float* llr_iter  = (const float*)d_in[2];
    const float* w_final   = (const float*)d_in[3];
    const float* llr_final = (const float*)d_in[4];
    const int*   vs_idx    = (const int*)  d_in[5];
    const int*   fin_idx   = (const int*)  d_in[9];
    const int*   edge_var  = (const int*)  d_in[11];
    float*       out       = (float*)d_out;

    const int B = in_sizes[0] / NVAR;

    prepack_kernel<<<ITERS, MCHK>>>(w_iter, llr_iter, vs_idx, edge_var,
                                    fin_idx, w_final);
    bp_decode2_kernel<<<(B + 1) / 2, MCHK>>>(llr, llr_final, out, B);
}

// round 5
// speedup vs baseline: 1.0219x; 1.0219x over previous
#include <cuda_runtime.h>

// Fixed problem structure (M=512 checks, N=1024 vars, SHIFTS=(0,7,101)):
//   E = 3072 edges, check degree 6, var degree 3.
//   edges sorted by (check,var) => check c owns edges [6c, 6c+6).
#define ITERS 5
#define MCHK  512
#define NVAR  1024
#define NEDGE 3072

#define LOG2E 1.4426950408889634f
#define LN2   0.6931471805599453f

// Batch-invariant scratch, slot-major [j][c] for coalescing.
// Messages circulate in log2 units: g_wlt = {w0, w1, llr_iter*log2e, pad}
// (ln2*log2e = 1 folds the unit change into prepack; g_wf = w_final*ln2).
// float4/int4/float2 packing: halves the LDG instruction count (LSU dispatch
// floor = 4 cyc/LDG was the suspected ~53us structural binder).
__device__ float4 g_wlt [ITERS * NEDGE];
__device__ int4   g_sib [NEDGE];          // {sib0, sib1, ev, pad}, translated to j*512+c
__device__ float2 g_fw  [NEDGE];          // {bitcast(fidx), w_final*ln2}

__global__ void prepack_kernel(const float* __restrict__ w_iter,
                               const float* __restrict__ llr_iter,
                               const int*   __restrict__ vs_idx,
                               const int*   __restrict__ edge_var,
                               const int*   __restrict__ fin_idx,
                               const float* __restrict__ w_final)
{
    const int c = threadIdx.x;
    const int t = blockIdx.x;
#pragma unroll
    for (int j = 0; j < 6; ++j) {
        const int e = 6 * c + j;
        g_wlt[t * NEDGE + j * MCHK + c] =
            make_float4(w_iter[t * 2 * NEDGE + 2 * e],
                        w_iter[t * 2 * NEDGE + 2 * e + 1],
                        llr_iter[t * NVAR + edge_var[e]] * LOG2E,
                        0.0f);
    }
    if (t == 0) {
#pragma unroll
        for (int j = 0; j < 6; ++j) {
            const int e  = 6 * c + j;
            const int s0 = vs_idx[2 * e];
            const int s1 = vs_idx[2 * e + 1];
            g_sib[j * MCHK + c] = make_int4((s0 % 6) * MCHK + s0 / 6,
                                            (s1 % 6) * MCHK + s1 / 6,
                                            edge_var[e], 0);
        }
#pragma unroll
        for (int k = 0; k < 2; ++k)
#pragma unroll
            for (int p = 0; p < 3; ++p) {
                const int v = c + MCHK * k;
                const int q = 3 * v + p;
                const int e = fin_idx[q];
                float2 fw;
                fw.x = __int_as_float((e % 6) * MCHK + e / 6);
                fw.y = w_final[q] * LN2;
                g_fw[(k * 3 + p) * MCHK + c] = fw;
            }
    }
}

__global__ __launch_bounds__(512, 2)
void bp_decode_kernel(const float* __restrict__ llr,        // [B, N]
                      const float* __restrict__ llr_final,  // [N]
                      float*       __restrict__ out)        // [B, N]
{
    __shared__ float sm[2][NEDGE];      // double-buffered c2v (log2 units)

    const int b = blockIdx.x;
    const int c = threadIdx.x;
    const float* __restrict__ llr_b = llr + (size_t)b * NVAR;

    int2  sib[6];
    float lv[6];
#pragma unroll
    for (int j = 0; j < 6; ++j) {
        const int4 s = g_sib[j * MCHK + c];    // 1 LDG.128 per j
        sib[j] = make_int2(s.x, s.y);
        lv[j]  = __ldg(&llr_b[s.z]);
    }

    float c2v[6];
#pragma unroll
    for (int j = 0; j < 6; ++j) c2v[j] = 0.0f;

    int cur = 0;
    for (int t = 0; t < ITERS; ++t) {
        // publish messages into the current buffer (conflict-free STS);
        // single barrier: the next iteration writes the OTHER buffer.
#pragma unroll
        for (int j = 0; j < 6; ++j) sm[cur][j * MCHK + c] = c2v[j];
        __syncthreads();

        const float4* __restrict__ wlt = g_wlt + t * NEDGE;

        // Variable update (rational form): v2c = (2^x-1)/(2^x+1)
        float n[6], d[6];
#pragma unroll
        for (int j = 0; j < 6; ++j) {
            const float4 w = wlt[j * MCHK + c];            // single LDG.128
            float x = sm[cur][sib[j].x] * w.x + sm[cur][sib[j].y] * w.y
                    + lv[j] * w.z;
            x = fminf(fmaxf(x, -25.0f), 25.0f);            // prod^5 overflow headroom
            const float ea = exp2f(x);                     // 1 MUFU
            n[j] = ea - 1.0f;
            d[j] = ea + 1.0f;
        }

        // Check update: exclusive products tracked as P/Q;
        //   c2v_l2 = log2(Q+P) - log2(Q-P)   (2 MUFU, no RCP)
        float sn[6], sd[6];
        sn[5] = 1.0f; sd[5] = 1.0f;
#pragma unroll
        for (int j = 4; j >= 0; --j) {
            sn[j] = sn[j + 1] * n[j + 1];
            sd[j] = sd[j + 1] * d[j + 1];
        }
        float pn = 0.9995f, pd = 1.0f;
#pragma unroll
        for (int j = 0; j < 6; ++j) {
            const float P = pn * sn[j];
            const float Q = pd * sd[j];
            c2v[j] = __log2f(Q + P) - __log2f(Q - P);
            pn *= n[j];
            pd *= d[j];
        }
        cur ^= 1;
    }

    // Epilogue: publish final messages, 2 variable outputs per thread.
#pragma unroll
    for (int j = 0; j < 6; ++j) sm[cur][j * MCHK + c] = c2v[j];
    __syncthreads();

    float* __restrict__ out_b = out + (size_t)b * NVAR;
#pragma unroll
    for (int k = 0; k < 2; ++k) {
        const int v = c + MCHK * k;
        float marg = 0.0f;
#pragma unroll
        for (int p = 0; p < 3; ++p) {
            const float2 fw = g_fw[(k * 3 + p) * MCHK + c];  // 1 LDG.64
            marg += sm[cur][__float_as_int(fw.x)] * fw.y;
        }
        marg += __ldg(&llr_b[v]) * llr_final[v];
        out_b[v] = __fdividef(1.0f, 1.0f + __expf(-marg));
    }
}

extern "C" void kernel_launch(void* const* d_in, const int* in_sizes, int n_in,
                              void* d_out, int out_size)
{
    // metadata order: llr, w_iter, llr_iter, w_final, llr_final,
    //                 v_sum_idx, seg_vsum, c_prod_idx, seg_cprod,
    //                 final_idx, seg_final, edge_var
    const float* llr       = (const float*)d_in[0];
    const float* w_iter    = (const float*)d_in[1];
    const float* llr_iter  = (const float*)d_in[2];
    const float* w_final   = (const float*)d_in[3];
    const float* llr_final = (const float*)d_in[4];
    const int*   vs_idx    = (const int*)  d_in[5];
    const int*   fin_idx   = (const int*)  d_in[9];
    const int*   edge_var  = (const int*)  d_in[11];
    float*       out       = (float*)d_out;

    const int B = in_sizes[0] / NVAR;

    prepack_kernel<<<ITERS, MCHK>>>(w_iter, llr_iter, vs_idx, edge_var,
                                    fin_idx, w_final);
    bp_decode_kernel<<<B, MCHK>>>(llr, llr_final, out);
}

// round 6
// speedup vs baseline: 1.4949x; 1.4629x over previous
#include <cuda_runtime.h>

// Fixed problem structure (M=512 checks, N=1024 vars, SHIFTS=(0,7,101)):
//   E = 3072 edges, check degree 6, var degree 3.
//   edges sorted by (check,var) => check c owns edges [6c, 6c+6).
#define ITERS 5
#define MCHK  512
#define NVAR  1024
#define NEDGE 3072

#define LOG2E 1.4426950408889634f
#define LN2   0.6931471805599453f

// Batch-invariant scratch, slot-major [j][c] for coalescing.
// Messages circulate in log2 units (g_wlt = {w0, w1, llr_iter*log2e, 0}).
__device__ int    g_fast;                 // 1 iff w_iter==1 && llr_iter==1 everywhere
__device__ float4 g_wlt [ITERS * NEDGE];  // general path only
__device__ int4   g_sib [NEDGE];          // {sib0*4, sib1*4, ev, 0} (byte offsets)
__device__ float2 g_fw  [NEDGE];          // {bitcast(fidx), w_final*ln2}

__global__ void flag_init_kernel() { g_fast = 1; }

__global__ void prepack_kernel(const float* __restrict__ w_iter,
                               const float* __restrict__ llr_iter,
                               const int*   __restrict__ vs_idx,
                               const int*   __restrict__ edge_var,
                               const int*   __restrict__ fin_idx,
                               const float* __restrict__ w_final)
{
    const int c = threadIdx.x;
    const int t = blockIdx.x;
    bool ok = true;
#pragma unroll
    for (int j = 0; j < 6; ++j) {
        const int e  = 6 * c + j;
        const float w0 = w_iter[t * 2 * NEDGE + 2 * e];
        const float w1 = w_iter[t * 2 * NEDGE + 2 * e + 1];
        const float li = llr_iter[t * NVAR + edge_var[e]];
        ok = ok && (w0 == 1.0f) && (w1 == 1.0f) && (li == 1.0f);
        g_wlt[t * NEDGE + j * MCHK + c] = make_float4(w0, w1, li * LOG2E, 0.0f);
    }
    if (!ok) g_fast = 0;   // only 0 is ever written -> race-free
    if (t == 0) {
#pragma unroll
        for (int j = 0; j < 6; ++j) {
            const int e  = 6 * c + j;
            const int s0 = vs_idx[2 * e];
            const int s1 = vs_idx[2 * e + 1];
            g_sib[j * MCHK + c] = make_int4(((s0 % 6) * MCHK + s0 / 6) * 4,
                                            ((s1 % 6) * MCHK + s1 / 6) * 4,
                                            edge_var[e], 0);
        }
#pragma unroll
        for (int k = 0; k < 2; ++k)
#pragma unroll
            for (int p = 0; p < 3; ++p) {
                const int v = c + MCHK * k;
                const int q = 3 * v + p;
                const int e = fin_idx[q];
                float2 fw;
                fw.x = __int_as_float((e % 6) * MCHK + e / 6);
                fw.y = w_final[q] * LN2;
                g_fw[(k * 3 + p) * MCHK + c] = fw;
            }
    }
}

__device__ __forceinline__ void check_update(const float x_in[6], float c2v[6])
{
    // v2c = (2^x-1)/(2^x+1) tracked as n/d; exclusive products as P/Q;
    // c2v_l2 = log2(Q+P) - log2(Q-P).  3 MUFU per edge, no RCP.
    float n[6], d[6];
#pragma unroll
    for (int j = 0; j < 6; ++j) {
        const float x  = fminf(fmaxf(x_in[j], -25.0f), 25.0f);
        const float ea = exp2f(x);
        n[j] = ea - 1.0f;
        d[j] = ea + 1.0f;
    }
    float sn[6], sd[6];
    sn[5] = 1.0f; sd[5] = 1.0f;
#pragma unroll
    for (int j = 4; j >= 0; --j) {
        sn[j] = sn[j + 1] * n[j + 1];
        sd[j] = sd[j + 1] * d[j + 1];
    }
    float pn = 0.9995f, pd = 1.0f;
#pragma unroll
    for (int j = 0; j < 6; ++j) {
        const float P = pn * sn[j];
        const float Q = pd * sd[j];
        c2v[j] = __log2f(Q + P) - __log2f(Q - P);
        pn *= n[j];
        pd *= d[j];
    }
}

__global__ __launch_bounds__(512, 2)
void bp_decode_kernel(const float* __restrict__ llr,        // [B, N]
                      const float* __restrict__ llr_final,  // [N]
                      float*       __restrict__ out)        // [B, N]
{
    __shared__ float sm[2][NEDGE];      // double-buffered c2v (log2 units)

    const int b = blockIdx.x;
    const int c = threadIdx.x;
    const float* __restrict__ llr_b = llr + (size_t)b * NVAR;

    int   sb0[6], sb1[6];
    float lv[6];
#pragma unroll
    for (int j = 0; j < 6; ++j) {
        const int4 s = g_sib[j * MCHK + c];    // 1 LDG.128 per j
        sb0[j] = s.x;  sb1[j] = s.y;
        lv[j]  = __ldg(&llr_b[s.z]);
    }

    float c2v[6];
    int cur = 0;

    if (g_fast) {
        // ---- fast path: all iteration weights are exactly 1.0 ----
        float lvs[6], x[6];
#pragma unroll
        for (int j = 0; j < 6; ++j) lvs[j] = lv[j] * LOG2E;

        // peeled iteration 0: incoming messages are all zero
        check_update(lvs, c2v);

#pragma unroll
        for (int t = 1; t < ITERS; ++t) {
            const char* smc = (const char*)sm[cur];
#pragma unroll
            for (int j = 0; j < 6; ++j) sm[cur][j * MCHK + c] = c2v[j];
            __syncthreads();
#pragma unroll
            for (int j = 0; j < 6; ++j) {
                const float m0 = *(const float*)(smc + sb0[j]);
                const float m1 = *(const float*)(smc + sb1[j]);
                x[j] = m0 + m1 + lvs[j];
            }
            check_update(x, c2v);
            cur ^= 1;
        }
    } else {
        // ---- general path: arbitrary per-iteration weights ----
        float x[6];
        {
            const float4* __restrict__ wlt = g_wlt;     // t = 0, messages zero
#pragma unroll
            for (int j = 0; j < 6; ++j) x[j] = lv[j] * wlt[j * MCHK + c].z;
            check_update(x, c2v);
        }
#pragma unroll
        for (int t = 1; t < ITERS; ++t) {
            const float4* __restrict__ wlt = g_wlt + t * NEDGE;
            const char* smc = (const char*)sm[cur];
#pragma unroll
            for (int j = 0; j < 6; ++j) sm[cur][j * MCHK + c] = c2v[j];
            __syncthreads();
#pragma unroll
            for (int j = 0; j < 6; ++j) {
                const float4 w  = wlt[j * MCHK + c];
                const float  m0 = *(const float*)(smc + sb0[j]);
                const float  m1 = *(const float*)(smc + sb1[j]);
                x[j] = m0 * w.x + m1 * w.y + lv[j] * w.z;
            }
            check_update(x, c2v);
            cur ^= 1;
        }
    }

    // Epilogue: publish final messages, 2 variable outputs per thread.
#pragma unroll
    for (int j = 0; j < 6; ++j) sm[cur][j * MCHK + c] = c2v[j];
    __syncthreads();

    float* __restrict__ out_b = out + (size_t)b * NVAR;
#pragma unroll
    for (int k = 0; k < 2; ++k) {
        const int v = c + MCHK * k;
        float marg = 0.0f;
#pragma unroll
        for (int p = 0; p < 3; ++p) {
            const float2 fw = g_fw[(k * 3 + p) * MCHK + c];  // 1 LDG.64
            marg += sm[cur][__float_as_int(fw.x)] * fw.y;
        }
        marg += __ldg(&llr_b[v]) * llr_final[v];
        out_b[v] = __fdividef(1.0f, 1.0f + __expf(-marg));
    }
}

extern "C" void kernel_launch(void* const* d_in, const int* in_sizes, int n_in,
                              void* d_out, int out_size)
{
    // metadata order: llr, w_iter, llr_iter, w_final, llr_final,
    //                 v_sum_idx, seg_vsum, c_prod_idx, seg_cprod,
    //                 final_idx, seg_final, edge_var
    const float* llr       = (const float*)d_in[0];
    const float* w_iter    = (const float*)d_in[1];
    const float* llr_iter  = (const float*)d_in[2];
    const float* w_final   = (const float*)d_in[3];
    const float* llr_final = (const float*)d_in[4];
    const int*   vs_idx    = (const int*)  d_in[5];
    const int*   fin_idx   = (const int*)  d_in[9];
    const int*   edge_var  = (const int*)  d_in[11];
    float*       out       = (float*)d_out;

    const int B = in_sizes[0] / NVAR;

    flag_init_kernel<<<1, 1>>>();
    prepack_kernel<<<ITERS, MCHK>>>(w_iter, llr_iter, vs_idx, edge_var,
                                    fin_idx, w_final);
    bp_decode_kernel<<<B, MCHK>>>(llr, llr_final, out);
}

// round 7
// speedup vs baseline: 1.9768x; 1.3224x over previous
#include <cuda_runtime.h>

// Fixed problem structure (M=512 checks, N=1024 vars, SHIFTS=(0,7,101)):
//   E = 3072 edges, check degree 6, var degree 3.
//   edges sorted by (check,var) => check c owns edges [6c, 6c+6).
#define ITERS 5
#define MCHK  512
#define NVAR  1024
#define NEDGE 3072

#define LOG2E 1.4426950408889634f
#define LN2   0.6931471805599453f

// g_fast: 1 iff w_iter==1 && llr_iter==1 everywhere (verified by prepack,
// which only ever writes 0 -> monotone, race-free, deterministic per input).
__device__ int    g_fast = 1;
__device__ float4 g_wlt [ITERS * NEDGE];  // general path: {w0, w1, llr_iter*log2e, 0}
__device__ int4   g_sib [NEDGE];          // {sib0*4, sib1*4, ev, 0} (byte offsets)
__device__ float2 g_fw  [NEDGE];          // {bitcast(fidx), w_final*ln2}

__global__ void prepack_kernel(const float* __restrict__ w_iter,
                               const float* __restrict__ llr_iter,
                               const int*   __restrict__ vs_idx,
                               const int*   __restrict__ edge_var,
                               const int*   __restrict__ fin_idx,
                               const float* __restrict__ w_final)
{
    const int c = threadIdx.x;
    const int t = blockIdx.x;
    bool ok = true;
#pragma unroll
    for (int j = 0; j < 6; ++j) {
        const int e  = 6 * c + j;
        const float w0 = w_iter[t * 2 * NEDGE + 2 * e];
        const float w1 = w_iter[t * 2 * NEDGE + 2 * e + 1];
        const float li = llr_iter[t * NVAR + edge_var[e]];
        ok = ok && (w0 == 1.0f) && (w1 == 1.0f) && (li == 1.0f);
        g_wlt[t * NEDGE + j * MCHK + c] = make_float4(w0, w1, li * LOG2E, 0.0f);
    }
    if (!ok) g_fast = 0;
    if (t == 0) {
#pragma unroll
        for (int j = 0; j < 6; ++j) {
            const int e  = 6 * c + j;
            const int s0 = vs_idx[2 * e];
            const int s1 = vs_idx[2 * e + 1];
            g_sib[j * MCHK + c] = make_int4(((s0 % 6) * MCHK + s0 / 6) * 4,
                                            ((s1 % 6) * MCHK + s1 / 6) * 4,
                                            edge_var[e], 0);
        }
#pragma unroll
        for (int k = 0; k < 2; ++k)
#pragma unroll
            for (int p = 0; p < 3; ++p) {
                const int v = c + MCHK * k;
                const int q = 3 * v + p;
                const int e = fin_idx[q];
                float2 fw;
                fw.x = __int_as_float((e % 6) * MCHK + e / 6);
                fw.y = w_final[q] * LN2;
                g_fw[(k * 3 + p) * MCHK + c] = fw;
            }
    }
}

// Exclusive products with the 0.9995 damping folded into the prefix seed:
// m[j] = 0.9995 * prod_{k != j} v[k]
__device__ __forceinline__ void excl_prod(const float v[6], float m[6])
{
    float pre[6], suf[6];
    pre[0] = 0.9995f;
    suf[5] = 1.0f;
#pragma unroll
    for (int j = 1; j < 6; ++j) pre[j] = pre[j - 1] * v[j - 1];
#pragma unroll
    for (int j = 4; j >= 0; --j) suf[j] = suf[j + 1] * v[j + 1];
#pragma unroll
    for (int j = 0; j < 6; ++j) m[j] = pre[j] * suf[j];
}

// General-path check update in log2 domain (see round-2 notes).
__device__ __forceinline__ void check_update_log(const float x_in[6], float c2v[6])
{
    float n[6], d[6];
#pragma unroll
    for (int j = 0; j < 6; ++j) {
        const float x  = fminf(fmaxf(x_in[j], -25.0f), 25.0f);
        const float ea = exp2f(x);
        n[j] = ea - 1.0f;
        d[j] = ea + 1.0f;
    }
    float sn[6], sd[6];
    sn[5] = 1.0f; sd[5] = 1.0f;
#pragma unroll
    for (int j = 4; j >= 0; --j) {
        sn[j] = sn[j + 1] * n[j + 1];
        sd[j] = sd[j + 1] * d[j + 1];
    }
    float pn = 0.9995f, pd = 1.0f;
#pragma unroll
    for (int j = 0; j < 6; ++j) {
        const float P = pn * sn[j];
        const float Q = pd * sd[j];
        c2v[j] = __log2f(Q + P) - __log2f(Q - P);
        pn *= n[j];
        pd *= d[j];
    }
}

__global__ __launch_bounds__(512, 2)
void bp_decode_kernel(const float* __restrict__ llr,        // [B, N]
                      const float* __restrict__ llr_final,  // [N]
                      float*       __restrict__ out)        // [B, N]
{
    __shared__ float sm[2][NEDGE];      // double-buffered messages

    const int b = blockIdx.x;
    const int c = threadIdx.x;
    const float* __restrict__ llr_b = llr + (size_t)b * NVAR;

    int   sb0[6], sb1[6];
    float lv[6];
#pragma unroll
    for (int j = 0; j < 6; ++j) {
        const int4 s = g_sib[j * MCHK + c];    // 1 LDG.128 per j
        sb0[j] = s.x;  sb1[j] = s.y;
        lv[j]  = __ldg(&llr_b[s.z]);
    }

    int cur = 0;
    const int fast = g_fast;

    if (fast) {
        // ======= fast path: unit weights -> pure tanh-domain loop, no logs =======
        // message m = tanh(c2v/2) = 0.9995 * prod v2c  (check node's native output)
        // variable update: v2c = tanh((c2v_a + c2v_b + llr)/2)
        //                      = combine(m_a, m_b, pl),  combine(x,y)=(x+y)/(1+xy)
        float pl[6];
#pragma unroll
        for (int j = 0; j < 6; ++j) {
            const float e = __expf(lv[j]);                  // pl = tanh(lv/2)
            pl[j] = 1.0f - __fdividef(2.0f, e + 1.0f);      // NaN-safe at +-inf
        }

        float m[6];
        excl_prod(pl, m);                                   // peeled iteration 0

#pragma unroll
        for (int t = 1; t < ITERS; ++t) {
            const char* smc = (const char*)sm[cur];
#pragma unroll
            for (int j = 0; j < 6; ++j) sm[cur][j * MCHK + c] = m[j];
            __syncthreads();

            float v2c[6];
#pragma unroll
            for (int j = 0; j < 6; ++j) {
                const float ma = *(const float*)(smc + sb0[j]);
                const float mb = *(const float*)(smc + sb1[j]);
                const float num1 = ma + mb;
                const float den1 = fmaf(ma, mb, 1.0f);
                const float num  = fmaf(pl[j], den1, num1);
                const float den  = fmaf(pl[j], num1, den1); // > 0 (|m|<=0.9995)
                v2c[j] = __fdividef(num, den);              // 1 MUFU per edge
            }
            excl_prod(v2c, m);
            cur ^= 1;
        }

        // epilogue: publish tanh-domain messages, convert with atanh once
#pragma unroll
        for (int j = 0; j < 6; ++j) sm[cur][j * MCHK + c] = m[j];
        __syncthreads();

        float* __restrict__ out_b = out + (size_t)b * NVAR;
#pragma unroll
        for (int k = 0; k < 2; ++k) {
            const int v = c + MCHK * k;
            float marg = 0.0f;
#pragma unroll
            for (int p = 0; p < 3; ++p) {
                const float2 fw = g_fw[(k * 3 + p) * MCHK + c];
                const float  mm = sm[cur][__float_as_int(fw.x)];
                // c2v/ln2 = log2(1+mm) - log2(1-mm);  fw.y prescaled by ln2
                marg += fw.y * (__log2f(1.0f + mm) - __log2f(1.0f - mm));
            }
            marg += __ldg(&llr_b[v]) * llr_final[v];
            out_b[v] = __fdividef(1.0f, 1.0f + __expf(-marg));
        }
    } else {
        // ======= general path: arbitrary weights, log2-domain messages =======
        float c2v[6], x[6];
        {
            const float4* __restrict__ wlt = g_wlt;         // t=0, messages zero
#pragma unroll
            for (int j = 0; j < 6; ++j) x[j] = lv[j] * wlt[j * MCHK + c].z;
            check_update_log(x, c2v);
        }
#pragma unroll
        for (int t = 1; t < ITERS; ++t) {
            const float4* __restrict__ wlt = g_wlt + t * NEDGE;
            const char* smc = (const char*)sm[cur];
#pragma unroll
            for (int j = 0; j < 6; ++j) sm[cur][j * MCHK + c] = c2v[j];
            __syncthreads();
#pragma unroll
            for (int j = 0; j < 6; ++j) {
                const float4 w  = wlt[j * MCHK + c];
                const float  m0 = *(const float*)(smc + sb0[j]);
                const float  m1 = *(const float*)(smc + sb1[j]);
                x[j] = m0 * w.x + m1 * w.y + lv[j] * w.z;
            }
            check_update_log(x, c2v);
            cur ^= 1;
        }

#pragma unroll
        for (int j = 0; j < 6; ++j) sm[cur][j * MCHK + c] = c2v[j];
        __syncthreads();

        float* __restrict__ out_b = out + (size_t)b * NVAR;
#pragma unroll
        for (int k = 0; k < 2; ++k) {
            const int v = c + MCHK * k;
            float marg = 0.0f;
#pragma unroll
            for (int p = 0; p < 3; ++p) {
                const float2 fw = g_fw[(k * 3 + p) * MCHK + c];
                marg += sm[cur][__float_as_int(fw.x)] * fw.y;
            }
            marg += __ldg(&llr_b[v]) * llr_final[v];
            out_b[v] = __fdividef(1.0f, 1.0f + __expf(-marg));
        }
    }
}

extern "C" void kernel_launch(void* const* d_in, const int* in_sizes, int n_in,
                              void* d_out, int out_size)
{
    // metadata order: llr, w_iter, llr_iter, w_final, llr_final,
    //                 v_sum_idx, seg_vsum, c_prod_idx, seg_cprod,
    //                 final_idx, seg_final, edge_var
    const float* llr       = (const float*)d_in[0];
    const float* w_iter    = (const float*)d_in[1];
    const float* llr_iter  = (const float*)d_in[2];
    const float* w_final   = (const float*)d_in[3];
    const float* llr_final = (const float*)d_in[4];
    const int*   vs_idx    = (const int*)  d_in[5];
    const int*   fin_idx   = (const int*)  d_in[9];
    const int*   edge_var  = (const int*)  d_in[11];
    float*       out       = (float*)d_out;

    const int B = in_sizes[0] / NVAR;

    prepack_kernel<<<ITERS, MCHK>>>(w_iter, llr_iter, vs_idx, edge_var,
                                    fin_idx, w_final);
    bp_decode_kernel<<<B, MCHK>>>(llr, llr_final, out);
}

// round 8
// speedup vs baseline: 2.3042x; 1.1656x over previous
#include <cuda_runtime.h>

// Fixed problem structure (M=512 checks, N=1024 vars, SHIFTS=(0,7,101)):
//   E = 3072 edges, check degree 6, var degree 3.
//   edges sorted by (check,var) => check c owns edges [6c, 6c+6).
#define ITERS 5
#define MCHK  512
#define NVAR  1024
#define NEDGE 3072

#define LOG2E 1.4426950408889634f
#define LN2   0.6931471805599453f

// g_fast: 1 iff w_iter==1 && llr_iter==1 everywhere (verified by prepack,
// which only ever writes 0 -> monotone, race-free, deterministic per input).
__device__ int    g_fast = 1;
__device__ float4 g_wlt [ITERS * NEDGE];  // general path: {w0, w1, llr_iter*log2e, 0}
__device__ int2   g_sib [NEDGE];          // {sib0_bytes | sib1_bytes<<16, ev}
__device__ float2 g_fw  [NEDGE];          // {bitcast(fidx), w_final*ln2}

__global__ void prepack_kernel(const float* __restrict__ w_iter,
                               const float* __restrict__ llr_iter,
                               const int*   __restrict__ vs_idx,
                               const int*   __restrict__ edge_var,
                               const int*   __restrict__ fin_idx,
                               const float* __restrict__ w_final)
{
    const int c = threadIdx.x;
    const int t = blockIdx.x;
    bool ok = true;
#pragma unroll
    for (int j = 0; j < 6; ++j) {
        const int e  = 6 * c + j;
        const float w0 = w_iter[t * 2 * NEDGE + 2 * e];
        const float w1 = w_iter[t * 2 * NEDGE + 2 * e + 1];
        const float li = llr_iter[t * NVAR + edge_var[e]];
        ok = ok && (w0 == 1.0f) && (w1 == 1.0f) && (li == 1.0f);
        g_wlt[t * NEDGE + j * MCHK + c] = make_float4(w0, w1, li * LOG2E, 0.0f);
    }
    if (!ok) g_fast = 0;
    if (t == 0) {
#pragma unroll
        for (int j = 0; j < 6; ++j) {
            const int e  = 6 * c + j;
            const int s0 = vs_idx[2 * e];
            const int s1 = vs_idx[2 * e + 1];
            const int b0 = ((s0 % 6) * MCHK + s0 / 6) * 4;   // byte offsets < 2^14
            const int b1 = ((s1 % 6) * MCHK + s1 / 6) * 4;
            g_sib[j * MCHK + c] = make_int2(b0 | (b1 << 16), edge_var[e]);
        }
#pragma unroll
        for (int k = 0; k < 2; ++k)
#pragma unroll
            for (int p = 0; p < 3; ++p) {
                const int v = c + MCHK * k;
                const int q = 3 * v + p;
                const int e = fin_idx[q];
                float2 fw;
                fw.x = __int_as_float((e % 6) * MCHK + e / 6);
                fw.y = w_final[q] * LN2;
                g_fw[(k * 3 + p) * MCHK + c] = fw;
            }
    }
}

// Exclusive products (pair-tree, depth 3, 14 muls), 0.9995 damping folded in:
// m[j] = 0.9995 * prod_{k != j} v[k]
__device__ __forceinline__ void excl_prod(const float v[6], float m[6])
{
    const float p01  = v[0] * v[1];
    const float p23  = v[2] * v[3];
    const float p45s = (0.9995f * v[4]) * v[5];
    const float B = p23 * p45s;           // excl {0,1}, scaled
    const float C = p01 * p45s;           // excl {2,3}, scaled
    const float D = 0.9995f * (p01 * p23);// excl {4,5}, scaled
    m[0] = v[1] * B;  m[1] = v[0] * B;
    m[2] = v[3] * C;  m[3] = v[2] * C;
    m[4] = v[5] * D;  m[5] = v[4] * D;
}

// General-path check update in log2 domain.
__device__ __forceinline__ void check_update_log(const float x_in[6], float c2v[6])
{
    float n[6], d[6];
#pragma unroll
    for (int j = 0; j < 6; ++j) {
        const float x  = fminf(fmaxf(x_in[j], -25.0f), 25.0f);
        const float ea = exp2f(x);
        n[j] = ea - 1.0f;
        d[j] = ea + 1.0f;
    }
    float sn[6], sd[6];
    sn[5] = 1.0f; sd[5] = 1.0f;
#pragma unroll
    for (int j = 4; j >= 0; --j) {
        sn[j] = sn[j + 1] * n[j + 1];
        sd[j] = sd[j + 1] * d[j + 1];
    }
    float pn = 0.9995f, pd = 1.0f;
#pragma unroll
    for (int j = 0; j < 6; ++j) {
        const float P = pn * sn[j];
        const float Q = pd * sd[j];
        c2v[j] = __log2f(Q + P) - __log2f(Q - P);
        pn *= n[j];
        pd *= d[j];
    }
}

__global__ __launch_bounds__(512, 3)
void bp_decode_kernel(const float* __restrict__ llr,        // [B, N]
                      const float* __restrict__ llr_final,  // [N]
                      float*       __restrict__ out)        // [B, N]
{
    __shared__ float sm[2][NEDGE];      // double-buffered messages

    const int b = blockIdx.x;
    const int c = threadIdx.x;
    const float* __restrict__ llr_b = llr + (size_t)b * NVAR;

    int sibpk[6];                       // packed {sb0 | sb1<<16}
    float pl[6];                        // pl = tanh(llr/2) on this edge's variable
#pragma unroll
    for (int j = 0; j < 6; ++j) {
        const int2 s = g_sib[j * MCHK + c];          // 1 LDG.64 per j
        sibpk[j] = s.x;
        const float lvj = __ldg(&llr_b[s.y]);
        const float e = __expf(lvj);
        pl[j] = 1.0f - __fdividef(2.0f, e + 1.0f);   // NaN-safe at +-inf
    }

    int cur = 0;
    if (g_fast) {
        // ======= fast path: unit weights -> tanh-domain loop, no logs =======
        // message m = tanh(c2v/2) = 0.9995 * prod v2c (check node's native output)
        // variable update: v2c = combine(combine(m_a, m_b), pl), combine=(x+y)/(1+xy)
        float m[6];
        excl_prod(pl, m);                            // peeled iteration 0

#pragma unroll
        for (int t = 1; t < ITERS; ++t) {
            const char* smc = (const char*)sm[cur];
#pragma unroll
            for (int j = 0; j < 6; ++j) sm[cur][j * MCHK + c] = m[j];
            __syncthreads();

            float v2c[6];
#pragma unroll
            for (int j = 0; j < 6; ++j) {
                const float ma = *(const float*)(smc + (sibpk[j] & 0xFFFF));
                const float mb = *(const float*)(smc + (sibpk[j] >> 16));
                const float num1 = ma + mb;
                const float den1 = fmaf(ma, mb, 1.0f);
                const float num  = fmaf(pl[j], den1, num1);
                const float den  = fmaf(pl[j], num1, den1); // > 0 (|m|<=0.9995)
                v2c[j] = __fdividef(num, den);
            }
            excl_prod(v2c, m);
            cur ^= 1;
        }

        // epilogue: publish tanh-domain messages, convert with atanh once
#pragma unroll
        for (int j = 0; j < 6; ++j) sm[cur][j * MCHK + c] = m[j];
        __syncthreads();

        float* __restrict__ out_b = out + (size_t)b * NVAR;
#pragma unroll
        for (int k = 0; k < 2; ++k) {
            const int v = c + MCHK * k;
            float marg = 0.0f;
#pragma unroll
            for (int p = 0; p < 3; ++p) {
                const float2 fw = g_fw[(k * 3 + p) * MCHK + c];
                const float  mm = sm[cur][__float_as_int(fw.x)];
                // c2v/ln2 = log2(1+mm) - log2(1-mm); fw.y prescaled by ln2
                marg += fw.y * (__log2f(1.0f + mm) - __log2f(1.0f - mm));
            }
            marg += __ldg(&llr_b[v]) * llr_final[v];
            out_b[v] = __fdividef(1.0f, 1.0f + __expf(-marg));
        }
    } else {
        // ======= general path: arbitrary weights, log2-domain messages =======
        float lv[6];
#pragma unroll
        for (int j = 0; j < 6; ++j) lv[j] = __ldg(&llr_b[g_sib[j * MCHK + c].y]);

        float c2v[6], x[6];
        {
            const float4* __restrict__ wlt = g_wlt;  // t=0, messages zero
#pragma unroll
            for (int j = 0; j < 6; ++j) x[j] = lv[j] * wlt[j * MCHK + c].z;
            check_update_log(x, c2v);
        }
#pragma unroll
        for (int t = 1; t < ITERS; ++t) {
            const float4* __restrict__ wlt = g_wlt + t * NEDGE;
            const char* smc = (const char*)sm[cur];
#pragma unroll
            for (int j = 0; j < 6; ++j) sm[cur][j * MCHK + c] = c2v[j];
            __syncthreads();
#pragma unroll
            for (int j = 0; j < 6; ++j) {
                const float4 w  = wlt[j * MCHK + c];
                const float  m0 = *(const float*)(smc + (sibpk[j] & 0xFFFF));
                const float  m1 = *(const float*)(smc + (sibpk[j] >> 16));
                x[j] = m0 * w.x + m1 * w.y + lv[j] * w.z;
            }
            check_update_log(x, c2v);
            cur ^= 1;
        }

#pragma unroll
        for (int j = 0; j < 6; ++j) sm[cur][j * MCHK + c] = c2v[j];
        __syncthreads();

        float* __restrict__ out_b = out + (size_t)b * NVAR;
#pragma unroll
        for (int k = 0; k < 2; ++k) {
            const int v = c + MCHK * k;
            float marg = 0.0f;
#pragma unroll
            for (int p = 0; p < 3; ++p) {
                const float2 fw = g_fw[(k * 3 + p) * MCHK + c];
                marg += sm[cur][__float_as_int(fw.x)] * fw.y;
            }
            marg += __ldg(&llr_b[v]) * llr_final[v];
            out_b[v] = __fdividef(1.0f, 1.0f + __expf(-marg));
        }
    }
}

extern "C" void kernel_launch(void* const* d_in, const int* in_sizes, int n_in,
                              void* d_out, int out_size)
{
    // metadata order: llr, w_iter, llr_iter, w_final, llr_final,
    //                 v_sum_idx, seg_vsum, c_prod_idx, seg_cprod,
    //                 final_idx, seg_final, edge_var
    const float* llr       = (const float*)d_in[0];
    const float* w_iter    = (const float*)d_in[1];
    const float* llr_iter  = (const float*)d_in[2];
    const float* w_final   = (const float*)d_in[3];
    const float* llr_final = (const float*)d_in[4];
    const int*   vs_idx    = (const int*)  d_in[5];
    const int*   fin_idx   = (const int*)  d_in[9];
    const int*   edge_var  = (const int*)  d_in[11];
    float*       out       = (float*)d_out;

    const int B = in_sizes[0] / NVAR;

    prepack_kernel<<<ITERS, MCHK>>>(w_iter, llr_iter, vs_idx, edge_var,
                                    fin_idx, w_final);
    bp_decode_kernel<<<B, MCHK>>>(llr, llr_final, out);
}